// round 4
// baseline (speedup 1.0000x reference)
#include <cuda_runtime.h>

// Problem constants
#define NPTS   65536      // B*S = 4*16384
#define C      64         // IN_C == OUT_C
#define KNB    16         // neighbors
#define MIDD   16         // attention MLP mid dim
#define PPB    4          // points per block
#define ROWS   (PPB*KNB)  // 64 neighbor rows per block
#define AS     68         // padded row stride for 64-wide smem buffers
#define HS     20         // padded row stride for H buffer (16-wide)
#define THREADS 256

// ---------------- transposed-weight scratch (device globals: no allocs) ----------------
__device__ float gWq_t[64*64];    // [c][o]
__device__ float gWk_t[64*64];
__device__ float gWv_t[64*64];
__device__ float gWpe2_t[64*64];
__device__ float gWproj_t[64*64];
__device__ float gWa1_t[64*16];   // [c][m]
__device__ float gWa2_t[16*64];   // [m][o]
__device__ float gWpe1_t[3*64];   // [d][o]

__global__ void prep_kernel(const float* __restrict__ Wq, const float* __restrict__ Wk,
                            const float* __restrict__ Wv, const float* __restrict__ Wpe1,
                            const float* __restrict__ Wpe2, const float* __restrict__ Wa1,
                            const float* __restrict__ Wa2, const float* __restrict__ Wproj) {
    int t = blockIdx.x * blockDim.x + threadIdx.x;
    if (t < 4096) {
        int o = t >> 6, c = t & 63;        // t = o*64 + c (row-major [o][c])
        gWq_t  [c*64 + o] = Wq[t];
        gWk_t  [c*64 + o] = Wk[t];
        gWv_t  [c*64 + o] = Wv[t];
        gWpe2_t[c*64 + o] = Wpe2[t];
        gWproj_t[c*64 + o] = Wproj[t];
    }
    if (t < 1024) {
        int m = t >> 6, c = t & 63;        // Wa1 is [16][64]
        gWa1_t[c*16 + m] = Wa1[t];
        int o = t >> 4, mm = t & 15;       // Wa2 is [64][16]
        gWa2_t[mm*64 + o] = Wa2[t];
    }
    if (t < 192) {
        int o = t / 3, d = t - o*3;        // Wpe1 is [64][3]
        gWpe1_t[d*64 + o] = Wpe1[t];
    }
}

// ---------------- register-tiled 2x8 GEMM helpers ----------------
// acc[r0..r0+1][o0..o0+7] += A(smem, KD cols, stride ASTR) * Wt(global, [KD][64])
template<int KD, int ASTR>
__device__ __forceinline__ void gemm_2x8(const float* sA, int r0, int o0,
                                         const float* __restrict__ Wt,
                                         float* acc0, float* acc1) {
#pragma unroll
    for (int c = 0; c < KD; c += 4) {
        float4 A0 = *reinterpret_cast<const float4*>(sA + r0*ASTR + c);
        float4 A1 = *reinterpret_cast<const float4*>(sA + (r0+1)*ASTR + c);
        float a0[4] = {A0.x, A0.y, A0.z, A0.w};
        float a1[4] = {A1.x, A1.y, A1.z, A1.w};
#pragma unroll
        for (int u = 0; u < 4; ++u) {
            float4 W0 = *reinterpret_cast<const float4*>(Wt + (c+u)*64 + o0);
            float4 W1 = *reinterpret_cast<const float4*>(Wt + (c+u)*64 + o0 + 4);
            float wv[8] = {W0.x,W0.y,W0.z,W0.w,W1.x,W1.y,W1.z,W1.w};
#pragma unroll
            for (int j = 0; j < 8; ++j) {
                acc0[j] = fmaf(a0[u], wv[j], acc0[j]);
                acc1[j] = fmaf(a1[u], wv[j], acc1[j]);
            }
        }
    }
}

// same, but two weight matrices sharing one A pass (kk & v)
template<int KD, int ASTR>
__device__ __forceinline__ void gemm_2x8_dual(const float* sA, int r0, int o0,
                                              const float* __restrict__ Wt1,
                                              const float* __restrict__ Wt2,
                                              float* k0, float* k1, float* v0, float* v1) {
#pragma unroll
    for (int c = 0; c < KD; c += 4) {
        float4 A0 = *reinterpret_cast<const float4*>(sA + r0*ASTR + c);
        float4 A1 = *reinterpret_cast<const float4*>(sA + (r0+1)*ASTR + c);
        float a0[4] = {A0.x, A0.y, A0.z, A0.w};
        float a1[4] = {A1.x, A1.y, A1.z, A1.w};
#pragma unroll
        for (int u = 0; u < 4; ++u) {
            float4 W0 = *reinterpret_cast<const float4*>(Wt1 + (c+u)*64 + o0);
            float4 W1 = *reinterpret_cast<const float4*>(Wt1 + (c+u)*64 + o0 + 4);
            float4 V0 = *reinterpret_cast<const float4*>(Wt2 + (c+u)*64 + o0);
            float4 V1 = *reinterpret_cast<const float4*>(Wt2 + (c+u)*64 + o0 + 4);
            float wk[8] = {W0.x,W0.y,W0.z,W0.w,W1.x,W1.y,W1.z,W1.w};
            float wv[8] = {V0.x,V0.y,V0.z,V0.w,V1.x,V1.y,V1.z,V1.w};
#pragma unroll
            for (int j = 0; j < 8; ++j) {
                k0[j] = fmaf(a0[u], wk[j], k0[j]);
                k1[j] = fmaf(a1[u], wk[j], k1[j]);
                v0[j] = fmaf(a0[u], wv[j], v0[j]);
                v1[j] = fmaf(a1[u], wv[j], v1[j]);
            }
        }
    }
}

// ---------------- main fused kernel ----------------
__global__ void __launch_bounds__(THREADS)
lab_kernel(const float* __restrict__ cxyz, const float* __restrict__ cfeat,
           const float* __restrict__ nxyz, const float* __restrict__ nfeat,
           const float* __restrict__ lnw,  const float* __restrict__ lnb,
           float* __restrict__ out) {
    extern __shared__ float sm[];
    float* sNF  = sm;                   // [64][AS]  neigh_feat -> later v+pe
    float* sPE  = sNF + ROWS*AS;        // [64][AS]  pe_raw -> later s = q-kk+pe
    float* sS   = sPE + ROWS*AS;        // [64][AS]  pe -> later w (attn logits)
    float* sH   = sS  + ROWS*AS;        // [64][HS]  h = relu(s @ Wa1^T)
    float* sREL = sH  + ROWS*HS;        // [64][4]   relative xyz
    float* sCF  = sREL + ROWS*4;        // [4][64]   center_feat
    float* sQ   = sCF + PPB*C;          // [4][64]   q -> later y (pre-LN)
    float* sO   = sQ  + PPB*C;          // [4][64]   attention output

    const int tid = threadIdx.x;
    const int p0  = blockIdx.x * PPB;   // first point of this block

    // ---- Stage A: load inputs into smem ----
    {
        const float4* nf4 = reinterpret_cast<const float4*>(nfeat + (size_t)p0*KNB*C);
#pragma unroll
        for (int j = tid; j < ROWS*C/4; j += THREADS) {
            float4 v = __ldcs(nf4 + j);
            int e = j*4; int r = e >> 6; int c = e & 63;
            *reinterpret_cast<float4*>(sNF + r*AS + c) = v;
        }
        if (tid < PPB*C/4) {
            float4 v = __ldcs(reinterpret_cast<const float4*>(cfeat + (size_t)p0*C) + tid);
            int e = tid*4; int i = e >> 6; int c = e & 63;
            *reinterpret_cast<float4*>(sCF + i*C + c) = v;
        }
        if (tid < ROWS) {
            int r = tid, i = r >> 4;
            float cx0 = __ldcs(cxyz + (p0+i)*3 + 0);
            float cx1 = __ldcs(cxyz + (p0+i)*3 + 1);
            float cx2 = __ldcs(cxyz + (p0+i)*3 + 2);
            int nb = (p0*KNB + r)*3;
            sREL[r*4+0] = __ldcs(nxyz + nb + 0) - cx0;
            sREL[r*4+1] = __ldcs(nxyz + nb + 1) - cx1;
            sREL[r*4+2] = __ldcs(nxyz + nb + 2) - cx2;
        }
    }
    __syncthreads();

    const int cg = tid & 7;       // col group: cols o0..o0+7
    const int rg = tid >> 3;      // row group: rows r0, r0+1
    const int r0 = rg*2, o0 = cg*8;

    // ---- Stage B: pe_raw = relu(rel @ Wpe1^T) -> sPE ;  q = cf @ Wq^T -> sQ ----
    {
        float acc0[8], acc1[8];
#pragma unroll
        for (int j = 0; j < 8; ++j) { acc0[j] = 0.f; acc1[j] = 0.f; }
#pragma unroll
        for (int d = 0; d < 3; ++d) {
            float a0 = sREL[r0*4 + d];
            float a1 = sREL[(r0+1)*4 + d];
            float4 W0 = *reinterpret_cast<const float4*>(gWpe1_t + d*64 + o0);
            float4 W1 = *reinterpret_cast<const float4*>(gWpe1_t + d*64 + o0 + 4);
            float wv[8] = {W0.x,W0.y,W0.z,W0.w,W1.x,W1.y,W1.z,W1.w};
#pragma unroll
            for (int j = 0; j < 8; ++j) {
                acc0[j] = fmaf(a0, wv[j], acc0[j]);
                acc1[j] = fmaf(a1, wv[j], acc1[j]);
            }
        }
#pragma unroll
        for (int j = 0; j < 8; ++j) {
            sPE[r0*AS + o0 + j]     = fmaxf(acc0[j], 0.f);
            sPE[(r0+1)*AS + o0 + j] = fmaxf(acc1[j], 0.f);
        }
        // q (one output per thread: 4 points x 64 channels = 256)
        int i = tid >> 6, o = tid & 63;
        float acc = 0.f;
#pragma unroll 4
        for (int c = 0; c < 64; ++c) acc = fmaf(sCF[i*C + c], gWq_t[c*64 + o], acc);
        sQ[i*C + o] = acc;
    }
    __syncthreads();

    // ---- Stage C: pe = pe_raw @ Wpe2^T -> sS ----
    {
        float acc0[8], acc1[8];
#pragma unroll
        for (int j = 0; j < 8; ++j) { acc0[j] = 0.f; acc1[j] = 0.f; }
        gemm_2x8<64, AS>(sPE, r0, o0, gWpe2_t, acc0, acc1);
#pragma unroll
        for (int j = 0; j < 8; ++j) {
            sS[r0*AS + o0 + j]     = acc0[j];
            sS[(r0+1)*AS + o0 + j] = acc1[j];
        }
    }
    __syncthreads();

    // ---- Stage D/E: kk & v in one A pass; s = q - kk + pe -> sPE ; vpe = v + pe -> sNF ----
    {
        float k0[8], k1[8], v0[8], v1[8];
#pragma unroll
        for (int j = 0; j < 8; ++j) { k0[j]=k1[j]=v0[j]=v1[j]=0.f; }
        gemm_2x8_dual<64, AS>(sNF, r0, o0, gWk_t, gWv_t, k0, k1, v0, v1);
        const int i0 = r0 >> 4;   // r0 even -> r0 and r0+1 belong to the same point
#pragma unroll
        for (int j = 0; j < 8; ++j) {
            float pe0 = sS[r0*AS + o0 + j];
            float pe1 = sS[(r0+1)*AS + o0 + j];
            float qv  = sQ[i0*C + o0 + j];
            sPE[r0*AS + o0 + j]     = qv - k0[j] + pe0;
            sPE[(r0+1)*AS + o0 + j] = qv - k1[j] + pe1;
            v0[j] += pe0;
            v1[j] += pe1;
        }
        __syncthreads();   // everyone done reading sNF
#pragma unroll
        for (int j = 0; j < 8; ++j) {
            sNF[r0*AS + o0 + j]     = v0[j];
            sNF[(r0+1)*AS + o0 + j] = v1[j];
        }
    }
    __syncthreads();

    // ---- Stage F: h = relu(s @ Wa1^T) -> sH  (64 rows x 16 mid) ----
    {
        int rgrp = tid >> 4, m = tid & 15;
        int rb = rgrp * 4;
        float acc[4] = {0.f, 0.f, 0.f, 0.f};
#pragma unroll
        for (int c = 0; c < 64; c += 4) {
            float w0 = gWa1_t[(c+0)*16 + m];
            float w1 = gWa1_t[(c+1)*16 + m];
            float w2 = gWa1_t[(c+2)*16 + m];
            float w3 = gWa1_t[(c+3)*16 + m];
#pragma unroll
            for (int j = 0; j < 4; ++j) {
                float4 a = *reinterpret_cast<const float4*>(sPE + (rb+j)*AS + c);
                acc[j] = fmaf(a.x, w0, acc[j]);
                acc[j] = fmaf(a.y, w1, acc[j]);
                acc[j] = fmaf(a.z, w2, acc[j]);
                acc[j] = fmaf(a.w, w3, acc[j]);
            }
        }
#pragma unroll
        for (int j = 0; j < 4; ++j) sH[(rb+j)*HS + m] = fmaxf(acc[j], 0.f);
    }
    __syncthreads();

    // ---- Stage G: w = h @ Wa2^T -> sS ----
    {
        float acc0[8], acc1[8];
#pragma unroll
        for (int j = 0; j < 8; ++j) { acc0[j] = 0.f; acc1[j] = 0.f; }
        gemm_2x8<16, HS>(sH, r0, o0, gWa2_t, acc0, acc1);
#pragma unroll
        for (int j = 0; j < 8; ++j) {
            sS[r0*AS + o0 + j]     = acc0[j];
            sS[(r0+1)*AS + o0 + j] = acc1[j];
        }
    }
    __syncthreads();

    // ---- Stage H: softmax over K (per channel) + weighted sum of (v+pe) -> sO ----
    {
        int i = tid >> 6, o = tid & 63;
        int rb = i * KNB;
        float wv[KNB];
        float mx = -1e30f;
#pragma unroll
        for (int k = 0; k < KNB; ++k) {
            wv[k] = sS[(rb+k)*AS + o];
            mx = fmaxf(mx, wv[k]);
        }
        float sum = 0.f;
#pragma unroll
        for (int k = 0; k < KNB; ++k) { wv[k] = __expf(wv[k] - mx); sum += wv[k]; }
        float inv = 1.f / sum;
        float acc = 0.f;
#pragma unroll
        for (int k = 0; k < KNB; ++k) acc = fmaf(wv[k], sNF[(rb+k)*AS + o], acc);
        sO[i*C + o] = acc * inv;
    }
    __syncthreads();

    // ---- Stage I: proj + residual -> sQ (reused as y) ----
    {
        int i = tid >> 6, o = tid & 63;
        float acc = sCF[i*C + o];   // residual (identity: in_c == out_c)
#pragma unroll 4
        for (int c = 0; c < 64; ++c) acc = fmaf(sO[i*C + c], gWproj_t[c*64 + o], acc);
        sQ[i*C + o] = acc;
    }
    __syncthreads();

    // ---- Stage J: LayerNorm (warp w handles point w) + global store ----
    {
        int w = tid >> 5, l = tid & 31;
        if (w < PPB) {
            float y0 = sQ[w*C + l];
            float y1 = sQ[w*C + l + 32];
            float s  = y0 + y1;
            float s2 = y0*y0 + y1*y1;
#pragma unroll
            for (int off = 16; off; off >>= 1) {
                s  += __shfl_xor_sync(0xFFFFFFFFu, s,  off);
                s2 += __shfl_xor_sync(0xFFFFFFFFu, s2, off);
            }
            float mu  = s * (1.f/64.f);
            float var = s2 * (1.f/64.f) - mu*mu;
            float rs  = rsqrtf(var + 1e-5f);
            int g = p0 + w;
            out[(size_t)g*C + l]      = (y0 - mu) * rs * lnw[l]      + lnb[l];
            out[(size_t)g*C + l + 32] = (y1 - mu) * rs * lnw[l + 32] + lnb[l + 32];
        }
    }
}

// ---------------- launch ----------------
extern "C" void kernel_launch(void* const* d_in, const int* in_sizes, int n_in,
                              void* d_out, int out_size) {
    (void)in_sizes; (void)n_in; (void)out_size;
    const float* cxyz  = (const float*)d_in[0];
    const float* cfeat = (const float*)d_in[1];
    const float* nxyz  = (const float*)d_in[2];
    const float* nfeat = (const float*)d_in[3];
    const float* Wq    = (const float*)d_in[4];
    const float* Wk    = (const float*)d_in[5];
    const float* Wv    = (const float*)d_in[6];
    const float* Wpe1  = (const float*)d_in[7];
    const float* Wpe2  = (const float*)d_in[8];
    const float* Wa1   = (const float*)d_in[9];
    const float* Wa2   = (const float*)d_in[10];
    const float* Wproj = (const float*)d_in[11];
    const float* lnw   = (const float*)d_in[12];
    const float* lnb   = (const float*)d_in[13];

    prep_kernel<<<16, 256>>>(Wq, Wk, Wv, Wpe1, Wpe2, Wa1, Wa2, Wproj);

    size_t smem = (size_t)(3*ROWS*AS + ROWS*HS + ROWS*4 + 3*PPB*C) * sizeof(float);
    cudaFuncSetAttribute(lab_kernel, cudaFuncAttributeMaxDynamicSharedMemorySize, (int)smem);
    lab_kernel<<<NPTS/PPB, THREADS, smem>>>(cxyz, cfeat, nxyz, nfeat, lnw, lnb, (float*)d_out);
}

// round 5
// speedup vs baseline: 2.0975x; 2.0975x over previous
#include <cuda_runtime.h>
#include <cstdint>

// Problem constants
#define NPTS   65536      // B*S = 4*16384
#define C      64         // IN_C == OUT_C
#define KNB    16         // neighbors
#define PPB    4          // points per block
#define ROWS   (PPB*KNB)  // 64 neighbor rows per block
#define AS     68         // padded row stride (17 float4s: odd -> conflict-free)
#define HS     20         // padded row stride for H buffer
#define THREADS 256

// ---------------- transposed-weight scratch (device globals: no allocs) ----------------
__device__ __align__(16) float gWq_t[4096];    // [c][o]
__device__ __align__(16) float gWkN_t[4096];   // [c][o], NEGATED
__device__ __align__(16) float gWv_t[4096];
__device__ __align__(16) float gWpe2_t[4096];
__device__ __align__(16) float gWproj_t[4096];
__device__ __align__(16) float gWa1_t[1024];   // [c][m]
__device__ __align__(16) float gWa2_t[1024];   // [m][o]
__device__ __align__(16) float gWpe1_t[192];   // [d][o]

__global__ void prep_kernel(const float* __restrict__ Wq, const float* __restrict__ Wk,
                            const float* __restrict__ Wv, const float* __restrict__ Wpe1,
                            const float* __restrict__ Wpe2, const float* __restrict__ Wa1,
                            const float* __restrict__ Wa2, const float* __restrict__ Wproj) {
    int t = blockIdx.x * blockDim.x + threadIdx.x;
    if (t < 4096) {
        int o = t >> 6, c = t & 63;        // row-major [o][c] source
        gWq_t  [c*64 + o] =  Wq[t];
        gWkN_t [c*64 + o] = -Wk[t];        // negated: s = q + pe + (A @ -Wk)
        gWv_t  [c*64 + o] =  Wv[t];
        gWpe2_t[c*64 + o] =  Wpe2[t];
        gWproj_t[c*64 + o] = Wproj[t];
    }
    if (t < 1024) {
        int m = t >> 6, c = t & 63;        // Wa1 is [16][64]
        gWa1_t[c*16 + m] = Wa1[t];
        int o = t >> 4, mm = t & 15;       // Wa2 is [64][16]
        gWa2_t[mm*64 + o] = Wa2[t];
    }
    if (t < 192) {
        int o = t / 3, d = t - o*3;        // Wpe1 is [64][3]
        gWpe1_t[d*64 + o] = Wpe1[t];
    }
}

// ---------------- f32x2 packed math helpers ----------------
__device__ __forceinline__ void fma2(uint64_t& d, uint64_t a, uint64_t b) {
    asm("fma.rn.f32x2 %0, %1, %2, %0;" : "+l"(d) : "l"(a), "l"(b));
}
__device__ __forceinline__ uint64_t add2(uint64_t a, uint64_t b) {
    uint64_t d; asm("add.rn.f32x2 %0, %1, %2;" : "=l"(d) : "l"(a), "l"(b)); return d;
}
__device__ __forceinline__ uint64_t pack2(float x, float y) {
    uint64_t d; asm("mov.b64 %0, {%1, %2};" : "=l"(d) : "f"(x), "f"(y)); return d;
}
__device__ __forceinline__ uint64_t dup2(float x) { return pack2(x, x); }
__device__ __forceinline__ void unpack2(uint64_t v, float& x, float& y) {
    asm("mov.b64 {%0, %1}, %2;" : "=f"(x), "=f"(y) : "l"(v));
}

// ---------------- main fused kernel ----------------
__global__ void __launch_bounds__(THREADS, 2)
lab_kernel(const float* __restrict__ cxyz, const float* __restrict__ cfeat,
           const float* __restrict__ nxyz, const float* __restrict__ nfeat,
           const float* __restrict__ lnw,  const float* __restrict__ lnb,
           float* __restrict__ out) {
    extern __shared__ float sm[];
    float* sNF   = sm;                 // [64][AS] neigh_feat -> later vpe
    float* sPE   = sNF  + 4352;        // [64][AS] pe_raw -> pe -> s -> w(logits)
    float* sH    = sPE  + 4352;        // [64][HS] h
    float* sREL  = sH   + 1280;        // [64][4]  relative xyz
    float* sCF   = sREL + 256;         // [4][64]  center_feat
    float* sQ    = sCF  + 256;         // [4][64]  q -> later y (pre-LN)
    float* sO    = sQ   + 256;         // [4][64]  attention output
    float* sWk   = sO   + 256;         // [64][64] -Wk^T
    float* sWv   = sWk  + 4096;        // [64][64] Wv^T
    float* sWpe2 = sWv  + 4096;        // [64][64] Wpe2^T
    float* sWa1  = sWpe2+ 4096;        // [64][16]
    float* sWa2  = sWa1 + 1024;        // [16][64]
    // total 25344 floats = 101376 B

    const int tid = threadIdx.x;
    const int p0  = blockIdx.x * PPB;
    const int w   = tid >> 5;          // warp 0..7 -> column block
    const int l   = tid & 31;          // lane -> rows l and l+32
    const int o0  = w * 8;
    const int ra  = l;
    const int rb  = l + 32;

    // ---- Stage A: load inputs + stage weights into smem ----
    {
        const float4* nf4 = reinterpret_cast<const float4*>(nfeat + (size_t)p0*KNB*C);
#pragma unroll
        for (int j = tid; j < ROWS*C/4; j += THREADS) {
            float4 v = __ldcs(nf4 + j);
            int e = j*4; int r = e >> 6; int c = e & 63;
            *reinterpret_cast<float4*>(sNF + r*AS + c) = v;
        }
        // weights (L2-resident)
        const float4* wk4 = reinterpret_cast<const float4*>(gWkN_t);
        const float4* wv4 = reinterpret_cast<const float4*>(gWv_t);
        const float4* wp4 = reinterpret_cast<const float4*>(gWpe2_t);
#pragma unroll
        for (int j = tid; j < 1024; j += THREADS) {
            reinterpret_cast<float4*>(sWk)[j]   = wk4[j];
            reinterpret_cast<float4*>(sWv)[j]   = wv4[j];
            reinterpret_cast<float4*>(sWpe2)[j] = wp4[j];
        }
        if (tid < 256) {
            reinterpret_cast<float4*>(sWa1)[tid] = reinterpret_cast<const float4*>(gWa1_t)[tid];
            reinterpret_cast<float4*>(sWa2)[tid] = reinterpret_cast<const float4*>(gWa2_t)[tid];
        }
        if (tid < PPB*C/4) {
            float4 v = __ldcs(reinterpret_cast<const float4*>(cfeat + (size_t)p0*C) + tid);
            int e = tid*4; int i = e >> 6; int c = e & 63;
            *reinterpret_cast<float4*>(sCF + i*C + c) = v;
        }
        if (tid < ROWS) {
            int r = tid, i = r >> 4;
            float cx0 = __ldcs(cxyz + (p0+i)*3 + 0);
            float cx1 = __ldcs(cxyz + (p0+i)*3 + 1);
            float cx2 = __ldcs(cxyz + (p0+i)*3 + 2);
            int nb = (p0*KNB + r)*3;
            sREL[r*4+0] = __ldcs(nxyz + nb + 0) - cx0;
            sREL[r*4+1] = __ldcs(nxyz + nb + 1) - cx1;
            sREL[r*4+2] = __ldcs(nxyz + nb + 2) - cx2;
        }
    }
    __syncthreads();

    // ---- Stage B: pe_raw = relu(rel @ Wpe1^T) -> sPE ;  q = cf @ Wq^T -> sQ ----
    {
        float acc0[8], acc1[8];
#pragma unroll
        for (int j = 0; j < 8; ++j) { acc0[j] = 0.f; acc1[j] = 0.f; }
#pragma unroll
        for (int d = 0; d < 3; ++d) {
            float a0 = sREL[ra*4 + d];
            float a1 = sREL[rb*4 + d];
            float4 W0 = *reinterpret_cast<const float4*>(gWpe1_t + d*64 + o0);
            float4 W1 = *reinterpret_cast<const float4*>(gWpe1_t + d*64 + o0 + 4);
            float wv[8] = {W0.x,W0.y,W0.z,W0.w,W1.x,W1.y,W1.z,W1.w};
#pragma unroll
            for (int j = 0; j < 8; ++j) {
                acc0[j] = fmaf(a0, wv[j], acc0[j]);
                acc1[j] = fmaf(a1, wv[j], acc1[j]);
            }
        }
        float4 s0a = {fmaxf(acc0[0],0.f), fmaxf(acc0[1],0.f), fmaxf(acc0[2],0.f), fmaxf(acc0[3],0.f)};
        float4 s0b = {fmaxf(acc0[4],0.f), fmaxf(acc0[5],0.f), fmaxf(acc0[6],0.f), fmaxf(acc0[7],0.f)};
        float4 s1a = {fmaxf(acc1[0],0.f), fmaxf(acc1[1],0.f), fmaxf(acc1[2],0.f), fmaxf(acc1[3],0.f)};
        float4 s1b = {fmaxf(acc1[4],0.f), fmaxf(acc1[5],0.f), fmaxf(acc1[6],0.f), fmaxf(acc1[7],0.f)};
        *reinterpret_cast<float4*>(sPE + ra*AS + o0)     = s0a;
        *reinterpret_cast<float4*>(sPE + ra*AS + o0 + 4) = s0b;
        *reinterpret_cast<float4*>(sPE + rb*AS + o0)     = s1a;
        *reinterpret_cast<float4*>(sPE + rb*AS + o0 + 4) = s1b;
        // q (4 points x 64 channels = 256 outputs)
        int i = tid >> 6, o = tid & 63;
        float acc = 0.f;
#pragma unroll 8
        for (int c = 0; c < 64; ++c) acc = fmaf(sCF[i*C + c], __ldg(gWq_t + c*64 + o), acc);
        sQ[i*C + o] = acc;
    }
    __syncthreads();

    // ---- Stage C: pe = pe_raw @ Wpe2^T (in-place into sPE) ----
    {
        uint64_t pc[2][4];
#pragma unroll
        for (int jp = 0; jp < 4; ++jp) { pc[0][jp] = 0ULL; pc[1][jp] = 0ULL; }
#pragma unroll
        for (int c = 0; c < 64; c += 4) {
            float4 A0 = *reinterpret_cast<const float4*>(sPE + ra*AS + c);
            float4 A1 = *reinterpret_cast<const float4*>(sPE + rb*AS + c);
            float a0v[4] = {A0.x,A0.y,A0.z,A0.w};
            float a1v[4] = {A1.x,A1.y,A1.z,A1.w};
#pragma unroll
            for (int u = 0; u < 4; ++u) {
                const float* wr = sWpe2 + (c+u)*64 + o0;
                ulonglong2 w01 = *reinterpret_cast<const ulonglong2*>(wr);
                ulonglong2 w23 = *reinterpret_cast<const ulonglong2*>(wr + 4);
                uint64_t d0 = dup2(a0v[u]), d1 = dup2(a1v[u]);
                fma2(pc[0][0], d0, w01.x); fma2(pc[0][1], d0, w01.y);
                fma2(pc[0][2], d0, w23.x); fma2(pc[0][3], d0, w23.y);
                fma2(pc[1][0], d1, w01.x); fma2(pc[1][1], d1, w01.y);
                fma2(pc[1][2], d1, w23.x); fma2(pc[1][3], d1, w23.y);
            }
        }
        __syncthreads();   // everyone done reading pe_raw
        *reinterpret_cast<ulonglong2*>(sPE + ra*AS + o0)     = make_ulonglong2(pc[0][0], pc[0][1]);
        *reinterpret_cast<ulonglong2*>(sPE + ra*AS + o0 + 4) = make_ulonglong2(pc[0][2], pc[0][3]);
        *reinterpret_cast<ulonglong2*>(sPE + rb*AS + o0)     = make_ulonglong2(pc[1][0], pc[1][1]);
        *reinterpret_cast<ulonglong2*>(sPE + rb*AS + o0 + 4) = make_ulonglong2(pc[1][2], pc[1][3]);
        // no sync needed: Stage D reads back only this thread's own (row, col) region
    }

    // ---- Stage D: kk(+neg) & v in one A pass; s = q - kk + pe -> sPE ; vpe = v + pe -> sNF ----
    {
        uint64_t ak[2][4], av[2][4];
        const int pa = l >> 4, pb = pa + 2;
#pragma unroll
        for (int jp = 0; jp < 4; ++jp) {
            uint64_t pe0 = *reinterpret_cast<const uint64_t*>(sPE + ra*AS + o0 + 2*jp);
            uint64_t pe1 = *reinterpret_cast<const uint64_t*>(sPE + rb*AS + o0 + 2*jp);
            uint64_t q0  = *reinterpret_cast<const uint64_t*>(sQ + pa*C + o0 + 2*jp);
            uint64_t q1  = *reinterpret_cast<const uint64_t*>(sQ + pb*C + o0 + 2*jp);
            ak[0][jp] = add2(q0, pe0); av[0][jp] = pe0;
            ak[1][jp] = add2(q1, pe1); av[1][jp] = pe1;
        }
#pragma unroll
        for (int c = 0; c < 64; c += 4) {
            float4 A0 = *reinterpret_cast<const float4*>(sNF + ra*AS + c);
            float4 A1 = *reinterpret_cast<const float4*>(sNF + rb*AS + c);
            float a0v[4] = {A0.x,A0.y,A0.z,A0.w};
            float a1v[4] = {A1.x,A1.y,A1.z,A1.w};
#pragma unroll
            for (int u = 0; u < 4; ++u) {
                const float* wkr = sWk + (c+u)*64 + o0;
                const float* wvr = sWv + (c+u)*64 + o0;
                ulonglong2 k01 = *reinterpret_cast<const ulonglong2*>(wkr);
                ulonglong2 k23 = *reinterpret_cast<const ulonglong2*>(wkr + 4);
                ulonglong2 v01 = *reinterpret_cast<const ulonglong2*>(wvr);
                ulonglong2 v23 = *reinterpret_cast<const ulonglong2*>(wvr + 4);
                uint64_t d0 = dup2(a0v[u]), d1 = dup2(a1v[u]);
                fma2(ak[0][0], d0, k01.x); fma2(ak[0][1], d0, k01.y);
                fma2(ak[0][2], d0, k23.x); fma2(ak[0][3], d0, k23.y);
                fma2(ak[1][0], d1, k01.x); fma2(ak[1][1], d1, k01.y);
                fma2(ak[1][2], d1, k23.x); fma2(ak[1][3], d1, k23.y);
                fma2(av[0][0], d0, v01.x); fma2(av[0][1], d0, v01.y);
                fma2(av[0][2], d0, v23.x); fma2(av[0][3], d0, v23.y);
                fma2(av[1][0], d1, v01.x); fma2(av[1][1], d1, v01.y);
                fma2(av[1][2], d1, v23.x); fma2(av[1][3], d1, v23.y);
            }
        }
        __syncthreads();   // everyone done reading sNF (neigh_feat)
        *reinterpret_cast<ulonglong2*>(sPE + ra*AS + o0)     = make_ulonglong2(ak[0][0], ak[0][1]);
        *reinterpret_cast<ulonglong2*>(sPE + ra*AS + o0 + 4) = make_ulonglong2(ak[0][2], ak[0][3]);
        *reinterpret_cast<ulonglong2*>(sPE + rb*AS + o0)     = make_ulonglong2(ak[1][0], ak[1][1]);
        *reinterpret_cast<ulonglong2*>(sPE + rb*AS + o0 + 4) = make_ulonglong2(ak[1][2], ak[1][3]);
        *reinterpret_cast<ulonglong2*>(sNF + ra*AS + o0)     = make_ulonglong2(av[0][0], av[0][1]);
        *reinterpret_cast<ulonglong2*>(sNF + ra*AS + o0 + 4) = make_ulonglong2(av[0][2], av[0][3]);
        *reinterpret_cast<ulonglong2*>(sNF + rb*AS + o0)     = make_ulonglong2(av[1][0], av[1][1]);
        *reinterpret_cast<ulonglong2*>(sNF + rb*AS + o0 + 4) = make_ulonglong2(av[1][2], av[1][3]);
    }
    __syncthreads();

    // ---- Stage F: h = relu(s @ Wa1^T) -> sH  (warp w owns mid pair 2w,2w+1) ----
    {
        const int m0 = 2*w;
        uint64_t h0 = 0ULL, h1 = 0ULL;
#pragma unroll
        for (int c = 0; c < 64; c += 4) {
            float4 A0 = *reinterpret_cast<const float4*>(sPE + ra*AS + c);
            float4 A1 = *reinterpret_cast<const float4*>(sPE + rb*AS + c);
            float a0v[4] = {A0.x,A0.y,A0.z,A0.w};
            float a1v[4] = {A1.x,A1.y,A1.z,A1.w};
#pragma unroll
            for (int u = 0; u < 4; ++u) {
                uint64_t wp = *reinterpret_cast<const uint64_t*>(sWa1 + (c+u)*16 + m0);
                fma2(h0, dup2(a0v[u]), wp);
                fma2(h1, dup2(a1v[u]), wp);
            }
        }
        float x, y;
        unpack2(h0, x, y);
        *reinterpret_cast<uint64_t*>(sH + ra*HS + m0) = pack2(fmaxf(x,0.f), fmaxf(y,0.f));
        unpack2(h1, x, y);
        *reinterpret_cast<uint64_t*>(sH + rb*HS + m0) = pack2(fmaxf(x,0.f), fmaxf(y,0.f));
    }
    __syncthreads();   // sH complete; also all reads of sPE(s) are done

    // ---- Stage G: wlogits = h @ Wa2^T -> sPE ----
    {
        uint64_t g[2][4];
#pragma unroll
        for (int jp = 0; jp < 4; ++jp) { g[0][jp] = 0ULL; g[1][jp] = 0ULL; }
#pragma unroll
        for (int m = 0; m < 16; m += 4) {
            float4 H0 = *reinterpret_cast<const float4*>(sH + ra*HS + m);
            float4 H1 = *reinterpret_cast<const float4*>(sH + rb*HS + m);
            float h0v[4] = {H0.x,H0.y,H0.z,H0.w};
            float h1v[4] = {H1.x,H1.y,H1.z,H1.w};
#pragma unroll
            for (int u = 0; u < 4; ++u) {
                const float* wr = sWa2 + (m+u)*64 + o0;
                ulonglong2 w01 = *reinterpret_cast<const ulonglong2*>(wr);
                ulonglong2 w23 = *reinterpret_cast<const ulonglong2*>(wr + 4);
                uint64_t d0 = dup2(h0v[u]), d1 = dup2(h1v[u]);
                fma2(g[0][0], d0, w01.x); fma2(g[0][1], d0, w01.y);
                fma2(g[0][2], d0, w23.x); fma2(g[0][3], d0, w23.y);
                fma2(g[1][0], d1, w01.x); fma2(g[1][1], d1, w01.y);
                fma2(g[1][2], d1, w23.x); fma2(g[1][3], d1, w23.y);
            }
        }
        // safe to write sPE directly: last cross-thread reads of sPE were in Stage F,
        // ordered before the sync after F
        *reinterpret_cast<ulonglong2*>(sPE + ra*AS + o0)     = make_ulonglong2(g[0][0], g[0][1]);
        *reinterpret_cast<ulonglong2*>(sPE + ra*AS + o0 + 4) = make_ulonglong2(g[0][2], g[0][3]);
        *reinterpret_cast<ulonglong2*>(sPE + rb*AS + o0)     = make_ulonglong2(g[1][0], g[1][1]);
        *reinterpret_cast<ulonglong2*>(sPE + rb*AS + o0 + 4) = make_ulonglong2(g[1][2], g[1][3]);
    }
    __syncthreads();

    // ---- Stage H: softmax over K + weighted sum of vpe -> sO ----
    {
        int i = tid >> 6, o = tid & 63;
        int rbase = i * KNB;
        float wv[KNB];
        float mx = -1e30f;
#pragma unroll
        for (int k = 0; k < KNB; ++k) {
            wv[k] = sPE[(rbase+k)*AS + o];
            mx = fmaxf(mx, wv[k]);
        }
        float sum = 0.f;
#pragma unroll
        for (int k = 0; k < KNB; ++k) { wv[k] = __expf(wv[k] - mx); sum += wv[k]; }
        float inv = 1.f / sum;
        float acc = 0.f;
#pragma unroll
        for (int k = 0; k < KNB; ++k) acc = fmaf(wv[k], sNF[(rbase+k)*AS + o], acc);
        sO[i*C + o] = acc * inv;
    }
    __syncthreads();

    // ---- Stage I: proj + residual -> sQ (reused as y) ----
    {
        int i = tid >> 6, o = tid & 63;
        float acc = sCF[i*C + o];
#pragma unroll 8
        for (int c = 0; c < 64; ++c) acc = fmaf(sO[i*C + c], __ldg(gWproj_t + c*64 + o), acc);
        sQ[i*C + o] = acc;
    }
    __syncthreads();

    // ---- Stage J: LayerNorm + global store ----
    {
        int wp = tid >> 5, lid = tid & 31;
        if (wp < PPB) {
            float y0 = sQ[wp*C + lid];
            float y1 = sQ[wp*C + lid + 32];
            float s  = y0 + y1;
            float s2 = y0*y0 + y1*y1;
#pragma unroll
            for (int off = 16; off; off >>= 1) {
                s  += __shfl_xor_sync(0xFFFFFFFFu, s,  off);
                s2 += __shfl_xor_sync(0xFFFFFFFFu, s2, off);
            }
            float mu  = s * (1.f/64.f);
            float var = s2 * (1.f/64.f) - mu*mu;
            float rs  = rsqrtf(var + 1e-5f);
            int g = p0 + wp;
            out[(size_t)g*C + lid]      = (y0 - mu) * rs * lnw[lid]      + lnb[lid];
            out[(size_t)g*C + lid + 32] = (y1 - mu) * rs * lnw[lid + 32] + lnb[lid + 32];
        }
    }
}

// ---------------- launch ----------------
extern "C" void kernel_launch(void* const* d_in, const int* in_sizes, int n_in,
                              void* d_out, int out_size) {
    (void)in_sizes; (void)n_in; (void)out_size;
    const float* cxyz  = (const float*)d_in[0];
    const float* cfeat = (const float*)d_in[1];
    const float* nxyz  = (const float*)d_in[2];
    const float* nfeat = (const float*)d_in[3];
    const float* Wq    = (const float*)d_in[4];
    const float* Wk    = (const float*)d_in[5];
    const float* Wv    = (const float*)d_in[6];
    const float* Wpe1  = (const float*)d_in[7];
    const float* Wpe2  = (const float*)d_in[8];
    const float* Wa1   = (const float*)d_in[9];
    const float* Wa2   = (const float*)d_in[10];
    const float* Wproj = (const float*)d_in[11];
    const float* lnw   = (const float*)d_in[12];
    const float* lnb   = (const float*)d_in[13];

    prep_kernel<<<16, 256>>>(Wq, Wk, Wv, Wpe1, Wpe2, Wa1, Wa2, Wproj);

    size_t smem = 25344 * sizeof(float);   // 101376 B -> 2 blocks/SM
    cudaFuncSetAttribute(lab_kernel, cudaFuncAttributeMaxDynamicSharedMemorySize, (int)smem);
    lab_kernel<<<NPTS/PPB, THREADS, smem>>>(cxyz, cfeat, nxyz, nfeat, lnw, lnb, (float*)d_out);
}